// round 2
// baseline (speedup 1.0000x reference)
#include <cuda_runtime.h>
#include <cstdint>
#include <cstddef>

#define U_N  100000
#define I_N  50000
#define DD   128
#define BB   4
#define LL   2
#define NNZC 500000

// ---------------- scratch (device globals: allocation-guard-safe) ----------
__device__ float g_ue [U_N * DD];          //  51.2 MB  current user embedding
__device__ float g_ie [I_N * DD];          //  25.6 MB  current item embedding
__device__ float g_ues[BB * U_N * DD];     // 204.8 MB  per-behavior user aggregation
__device__ float g_ies[BB * I_N * DD];     // 102.4 MB  per-behavior item aggregation
__device__ float g_su [BB * U_N * DD];     // 204.8 MB  Z / sigmoid(Z) per layer (users)
__device__ float g_si [BB * I_N * DD];     // 102.4 MB  Z / sigmoid(Z) per layer (items)

__device__ __forceinline__ unsigned smem_u32(const void* p) {
    return (unsigned)__cvta_generic_to_shared(p);
}
__device__ __forceinline__ float sigf(float x) {
    return 1.0f / (1.0f + __expf(-x));
}

// ---------------- SPMM: one warp per edge, vector RED scatter --------------
// dst[b, d, :] += v * src[s, :]
__global__ void __launch_bounds__(256) spmm_kernel(
    const int* __restrict__ ridx, const int* __restrict__ cidx,
    const float* __restrict__ vals, const float* __restrict__ src,
    float* __restrict__ dst, int total, int nnz, int ndst, int dst_rows)
{
    int g = blockIdx.x * blockDim.x + threadIdx.x;
    int e = g >> 5;
    if (e >= total) return;
    int lane = g & 31;
    int r = __ldg(ridx + e);
    int c = __ldg(cidx + e);
    float v = __ldg(vals + e);
    int d = dst_rows ? r : c;
    int s = dst_rows ? c : r;
    int b = e / nnz;
    float4 x = __ldg(reinterpret_cast<const float4*>(src + (size_t)s * DD) + lane);
    float* p = dst + ((size_t)b * ndst + d) * DD + (size_t)lane * 4;
    asm volatile("red.global.add.v4.f32 [%0], {%1,%2,%3,%4};"
                 :: "l"(p), "f"(v * x.x), "f"(v * x.y), "f"(v * x.z), "f"(v * x.w)
                 : "memory");
}

// ---------------- GEMM: Y[N,128] = X[N,128] @ W[128,128] (+= if acc) -------
// 256 threads/block, 128-row x 128-col tile, 8x8 per-thread tile,
// packed fma.rn.f32x2 inner loop (rows paired in 64-bit accumulators).
#define XS_STRIDE 136
#define WS_STRIDE 132
#define GEMM_SMEM ((128 * XS_STRIDE + 128 * WS_STRIDE) * 4)

__global__ void __launch_bounds__(256) gemm128_kernel(
    const float* __restrict__ X, const float* __restrict__ W,
    float* __restrict__ Y, int N, int accFlag)
{
    extern __shared__ float sm[];
    float* XsT = sm;                       // [k=128][row=136 pad]  (transposed)
    float* Ws  = sm + 128 * XS_STRIDE;     // [k=128][col=132 pad]
    const int tid = threadIdx.x;
    const int r0  = blockIdx.x << 7;

    // load W [128x128], row = k, cols contiguous
    for (int i = tid; i < 128 * 32; i += 256) {
        int row = i >> 5;
        int c4  = (i & 31) << 2;
        float4 w = *reinterpret_cast<const float4*>(W + row * 128 + c4);
        *reinterpret_cast<float4*>(&Ws[row * WS_STRIDE + c4]) = w;
    }
    // load X tile transposed: XsT[k][row]
    for (int i = tid; i < 128 * 32; i += 256) {
        int row = i >> 5;
        int c4  = (i & 31) << 2;
        float4 x = make_float4(0.f, 0.f, 0.f, 0.f);
        int gr = r0 + row;
        if (gr < N) x = *reinterpret_cast<const float4*>(X + (size_t)gr * 128 + c4);
        XsT[(c4 + 0) * XS_STRIDE + row] = x.x;
        XsT[(c4 + 1) * XS_STRIDE + row] = x.y;
        XsT[(c4 + 2) * XS_STRIDE + row] = x.z;
        XsT[(c4 + 3) * XS_STRIDE + row] = x.w;
    }
    __syncthreads();

    const int m0 = (tid >> 4) << 3;   // row offset (0..120)
    const int c0 = (tid & 15) << 3;   // col offset (0..120)
    const unsigned xs_base = smem_u32(XsT) + m0 * 4;
    const unsigned ws_base = smem_u32(Ws)  + c0 * 4;

    unsigned long long acc[4][8];
    #pragma unroll
    for (int j = 0; j < 4; j++)
        #pragma unroll
        for (int n = 0; n < 8; n++) acc[j][n] = 0ULL;

    #pragma unroll 4
    for (int k = 0; k < 128; k++) {
        unsigned long long a0, a1, a2, a3;       // row pairs (m0+0,1),(2,3),(4,5),(6,7)
        unsigned xa = xs_base + (unsigned)k * (XS_STRIDE * 4);
        asm volatile("ld.shared.v2.u64 {%0,%1}, [%2];" : "=l"(a0), "=l"(a1) : "r"(xa));
        asm volatile("ld.shared.v2.u64 {%0,%1}, [%2];" : "=l"(a2), "=l"(a3) : "r"(xa + 16));
        float b0, b1, b2, b3, b4, b5, b6, b7;
        unsigned wa = ws_base + (unsigned)k * (WS_STRIDE * 4);
        asm volatile("ld.shared.v4.f32 {%0,%1,%2,%3}, [%4];"
                     : "=f"(b0), "=f"(b1), "=f"(b2), "=f"(b3) : "r"(wa));
        asm volatile("ld.shared.v4.f32 {%0,%1,%2,%3}, [%4];"
                     : "=f"(b4), "=f"(b5), "=f"(b6), "=f"(b7) : "r"(wa + 16));
        unsigned long long bb[8];
        asm("mov.b64 %0, {%1,%1};" : "=l"(bb[0]) : "f"(b0));
        asm("mov.b64 %0, {%1,%1};" : "=l"(bb[1]) : "f"(b1));
        asm("mov.b64 %0, {%1,%1};" : "=l"(bb[2]) : "f"(b2));
        asm("mov.b64 %0, {%1,%1};" : "=l"(bb[3]) : "f"(b3));
        asm("mov.b64 %0, {%1,%1};" : "=l"(bb[4]) : "f"(b4));
        asm("mov.b64 %0, {%1,%1};" : "=l"(bb[5]) : "f"(b5));
        asm("mov.b64 %0, {%1,%1};" : "=l"(bb[6]) : "f"(b6));
        asm("mov.b64 %0, {%1,%1};" : "=l"(bb[7]) : "f"(b7));
        #pragma unroll
        for (int n = 0; n < 8; n++) {
            asm("fma.rn.f32x2 %0, %1, %2, %0;" : "+l"(acc[0][n]) : "l"(a0), "l"(bb[n]));
            asm("fma.rn.f32x2 %0, %1, %2, %0;" : "+l"(acc[1][n]) : "l"(a1), "l"(bb[n]));
            asm("fma.rn.f32x2 %0, %1, %2, %0;" : "+l"(acc[2][n]) : "l"(a2), "l"(bb[n]));
            asm("fma.rn.f32x2 %0, %1, %2, %0;" : "+l"(acc[3][n]) : "l"(a3), "l"(bb[n]));
        }
    }

    // epilogue
    #pragma unroll
    for (int j = 0; j < 4; j++) {
        float lo[8], hi[8];
        #pragma unroll
        for (int n = 0; n < 8; n++)
            asm("mov.b64 {%0,%1}, %2;" : "=f"(lo[n]), "=f"(hi[n]) : "l"(acc[j][n]));
        #pragma unroll
        for (int h = 0; h < 2; h++) {
            int gr = r0 + m0 + j * 2 + h;
            if (gr < N) {
                const float* v = h ? hi : lo;
                float* p = Y + (size_t)gr * 128 + c0;
                float4 o0 = make_float4(v[0], v[1], v[2], v[3]);
                float4 o1 = make_float4(v[4], v[5], v[6], v[7]);
                if (accFlag) {
                    float4 y0 = *reinterpret_cast<float4*>(p);
                    float4 y1 = *reinterpret_cast<float4*>(p + 4);
                    o0.x += y0.x; o0.y += y0.y; o0.z += y0.z; o0.w += y0.w;
                    o1.x += y1.x; o1.y += y1.y; o1.z += y1.z; o1.w += y1.w;
                }
                *reinterpret_cast<float4*>(p)     = o0;
                *reinterpret_cast<float4*>(p + 4) = o1;
            }
        }
    }
}

// ---------------- combine: Z[b] <- sigmoid(Z[b]) (in place),
//                  E <- sigmoid(mean_b Z[b])  -------------------------------
__global__ void __launch_bounds__(256) combine_kernel(
    float* __restrict__ Z, float* __restrict__ E, int N)
{
    size_t i = (size_t)blockIdx.x * 256 + threadIdx.x;
    size_t tot = (size_t)N * 32;
    if (i >= tot) return;
    size_t o  = i * 4;
    size_t bs = (size_t)N * 128;
    float4 z0 = *reinterpret_cast<float4*>(Z + o);
    float4 z1 = *reinterpret_cast<float4*>(Z + o + bs);
    float4 z2 = *reinterpret_cast<float4*>(Z + o + 2 * bs);
    float4 z3 = *reinterpret_cast<float4*>(Z + o + 3 * bs);
    float4 m;
    m.x = sigf((z0.x + z1.x + z2.x + z3.x) * 0.25f);
    m.y = sigf((z0.y + z1.y + z2.y + z3.y) * 0.25f);
    m.z = sigf((z0.z + z1.z + z2.z + z3.z) * 0.25f);
    m.w = sigf((z0.w + z1.w + z2.w + z3.w) * 0.25f);
    *reinterpret_cast<float4*>(E + o) = m;
    z0.x = sigf(z0.x); z0.y = sigf(z0.y); z0.z = sigf(z0.z); z0.w = sigf(z0.w);
    z1.x = sigf(z1.x); z1.y = sigf(z1.y); z1.z = sigf(z1.z); z1.w = sigf(z1.w);
    z2.x = sigf(z2.x); z2.y = sigf(z2.y); z2.z = sigf(z2.z); z2.w = sigf(z2.w);
    z3.x = sigf(z3.x); z3.y = sigf(z3.y); z3.z = sigf(z3.z); z3.w = sigf(z3.w);
    *reinterpret_cast<float4*>(Z + o)          = z0;
    *reinterpret_cast<float4*>(Z + o + bs)     = z1;
    *reinterpret_cast<float4*>(Z + o + 2 * bs) = z2;
    *reinterpret_cast<float4*>(Z + o + 3 * bs) = z3;
}

// ---------------- launch ---------------------------------------------------
extern "C" void kernel_launch(void* const* d_in, const int* in_sizes, int n_in,
                              void* d_out, int out_size)
{
    const float* user_emb = (const float*)d_in[0];
    const float* item_emb = (const float*)d_in[1];
    const int*   rows     = (const int*)  d_in[2];
    const int*   cols     = (const int*)  d_in[3];
    const float* vals     = (const float*)d_in[4];
    const float* u_w      = (const float*)d_in[5];
    const float* i_w      = (const float*)d_in[6];
    const float* u_cat_w  = (const float*)d_in[7];
    const float* i_cat_w  = (const float*)d_in[8];
    float* out = (float*)d_out;

    static bool configured = false;
    if (!configured) {
        cudaFuncSetAttribute(gemm128_kernel,
                             cudaFuncAttributeMaxDynamicSharedMemorySize, GEMM_SMEM);
        configured = true;
    }

    float *ue, *ie, *ues, *ies, *su, *si;
    cudaGetSymbolAddress((void**)&ue,  g_ue);
    cudaGetSymbolAddress((void**)&ie,  g_ie);
    cudaGetSymbolAddress((void**)&ues, g_ues);
    cudaGetSymbolAddress((void**)&ies, g_ies);
    cudaGetSymbolAddress((void**)&su,  g_su);
    cudaGetSymbolAddress((void**)&si,  g_si);

    cudaMemcpyAsync(ue, user_emb, (size_t)U_N * DD * 4, cudaMemcpyDeviceToDevice);
    cudaMemcpyAsync(ie, item_emb, (size_t)I_N * DD * 4, cudaMemcpyDeviceToDevice);

    float* out_ue  = out;                               // user_embed  [U,D]
    float* out_ie  = out + (size_t)U_N * DD;            // item_embed  [I,D]
    float* out_ues = out_ie + (size_t)I_N * DD;         // user_embeds [B,U,D]
    float* out_ies = out_ues + (size_t)BB * U_N * DD;   // item_embeds [B,I,D]

    const int totE = BB * NNZC;                         // 2,000,000 edges
    const int spmmBl = (int)(((long long)totE * 32 + 255) / 256);

    for (int l = 0; l < LL; l++) {
        cudaMemsetAsync(ues, 0, (size_t)BB * U_N * DD * 4);
        cudaMemsetAsync(ies, 0, (size_t)BB * I_N * DD * 4);

        // both spmms read the PRE-update ue/ie (stream-ordered before combine)
        spmm_kernel<<<spmmBl, 256>>>(rows, cols, vals, ie, ues, totE, NNZC, U_N, 1);
        spmm_kernel<<<spmmBl, 256>>>(rows, cols, vals, ue, ies, totE, NNZC, I_N, 0);

        // Z = ues @ u_w[l] (all behaviors as one [B*U,128] GEMM), same items
        gemm128_kernel<<<(BB * U_N + 127) / 128, 256, GEMM_SMEM>>>(
            ues, u_w + (size_t)l * DD * DD, su, BB * U_N, 0);
        gemm128_kernel<<<(BB * I_N + 127) / 128, 256, GEMM_SMEM>>>(
            ies, i_w + (size_t)l * DD * DD, si, BB * I_N, 0);

        // sigmoid in place; ue/ie <- sigmoid(mean_b Z) (mean@W == mean of Z)
        combine_kernel<<<(U_N * 32 + 255) / 256, 256>>>(su, ue, U_N);
        combine_kernel<<<(I_N * 32 + 255) / 256, 256>>>(si, ie, I_N);

        // concat-GEMM as per-layer accumulation into the output
        int acc = (l > 0) ? 1 : 0;
        gemm128_kernel<<<(U_N + 127) / 128, 256, GEMM_SMEM>>>(
            ue, u_cat_w + (size_t)l * DD * DD, out_ue, U_N, acc);
        gemm128_kernel<<<(I_N + 127) / 128, 256, GEMM_SMEM>>>(
            ie, i_cat_w + (size_t)l * DD * DD, out_ie, I_N, acc);
        gemm128_kernel<<<(BB * U_N + 127) / 128, 256, GEMM_SMEM>>>(
            su, u_cat_w + (size_t)l * DD * DD, out_ues, BB * U_N, acc);
        gemm128_kernel<<<(BB * I_N + 127) / 128, 256, GEMM_SMEM>>>(
            si, i_cat_w + (size_t)l * DD * DD, out_ies, BB * I_N, acc);
    }
}

// round 5
// speedup vs baseline: 1.1171x; 1.1171x over previous
#include <cuda_runtime.h>
#include <cstdint>
#include <cstddef>

#define U_N  100000
#define I_N  50000
#define DD   128
#define BB   4
#define LL   2
#define NNZC 500000

// ---------------- scratch (device globals: allocation-guard-safe) ----------
__device__ float g_ue [U_N * DD];
__device__ float g_ie [I_N * DD];
__device__ float g_ues[BB * U_N * DD];
__device__ float g_ies[BB * I_N * DD];
__device__ float g_su [BB * U_N * DD];
__device__ float g_si [BB * I_N * DD];

__device__ __forceinline__ unsigned smem_u32(const void* p) {
    return (unsigned)__cvta_generic_to_shared(p);
}
__device__ __forceinline__ float sigf(float x) {
    return 1.0f / (1.0f + __expf(-x));
}

// ---------------- SPMM: one warp per edge, vector RED scatter --------------
__global__ void __launch_bounds__(256) spmm_kernel(
    const int* __restrict__ ridx, const int* __restrict__ cidx,
    const float* __restrict__ vals, const float* __restrict__ src,
    float* __restrict__ dst, int total, int nnz, int ndst, int dst_rows)
{
    int g = blockIdx.x * blockDim.x + threadIdx.x;
    int e = g >> 5;
    if (e >= total) return;
    int lane = g & 31;
    int r = __ldg(ridx + e);
    int c = __ldg(cidx + e);
    float v = __ldg(vals + e);
    int d = dst_rows ? r : c;
    int s = dst_rows ? c : r;
    int b = e / nnz;
    float4 x = __ldg(reinterpret_cast<const float4*>(src + (size_t)s * DD) + lane);
    float* p = dst + ((size_t)b * ndst + d) * DD + (size_t)lane * 4;
    asm volatile("red.global.add.v4.f32 [%0], {%1,%2,%3,%4};"
                 :: "l"(p), "f"(v * x.x), "f"(v * x.y), "f"(v * x.z), "f"(v * x.w)
                 : "memory");
}

// ---------------- GEMM: Y[N,128] = X[N,128] @ W[128,128] (+= if acc) -------
// 256 threads/block, 256-row x 128-col block tile, 16x8 per-thread tile.
// X kept ROW-MAJOR in smem (conflict-free stores; broadcast scalar loads).
// Inner product via packed fma.rn.f32x2 (row pairs in 64-bit accumulators).
#define RPB       256                    // rows per block
#define XS_STRIDE 132
#define WS_STRIDE 132
#define GEMM_SMEM ((RPB * XS_STRIDE + 128 * WS_STRIDE) * 4)   // 202,752 B

__global__ void __launch_bounds__(256, 1) gemm128_kernel(
    const float* __restrict__ X, const float* __restrict__ W,
    float* __restrict__ Y, int N, int accFlag)
{
    extern __shared__ float sm[];
    float* Xs = sm;                        // [256][132] row-major
    float* Ws = sm + RPB * XS_STRIDE;      // [128][132] row = k
    const int tid = threadIdx.x;
    const int r0  = blockIdx.x * RPB;

    // load W [128x128] (coalesced, conflict-free)
    for (int i = tid; i < 128 * 32; i += 256) {
        int row = i >> 5;
        int c4  = (i & 31) << 2;
        float4 w = *reinterpret_cast<const float4*>(W + row * 128 + c4);
        *reinterpret_cast<float4*>(&Ws[row * WS_STRIDE + c4]) = w;
    }
    // load X tile rows r0..r0+255 ROW-MAJOR (coalesced, conflict-free)
    for (int i = tid; i < RPB * 32; i += 256) {
        int row = i >> 5;
        int c4  = (i & 31) << 2;
        float4 x = make_float4(0.f, 0.f, 0.f, 0.f);
        int gr = r0 + row;
        if (gr < N) x = *reinterpret_cast<const float4*>(X + (size_t)gr * 128 + c4);
        *reinterpret_cast<float4*>(&Xs[row * XS_STRIDE + c4]) = x;
    }
    __syncthreads();

    const int m0 = (tid >> 4) << 4;   // row offset 0..240 (16 rows/thread)
    const int c0 = (tid & 15) << 3;   // col offset 0..120 (8 cols/thread)
    const unsigned xs_base = smem_u32(Xs) + (unsigned)m0 * (XS_STRIDE * 4);
    const unsigned ws_base = smem_u32(Ws) + (unsigned)c0 * 4;

    unsigned long long acc[8][8];     // 8 row-pairs x 8 cols
    #pragma unroll
    for (int j = 0; j < 8; j++)
        #pragma unroll
        for (int n = 0; n < 8; n++) acc[j][n] = 0ULL;

    #pragma unroll 2
    for (int k = 0; k < 128; k++) {
        // 16 broadcast scalar loads (half-warp-uniform addresses)
        float xv[16];
        unsigned xa = xs_base + (unsigned)k * 4;
        #pragma unroll
        for (int j = 0; j < 16; j++)
            asm volatile("ld.shared.f32 %0, [%1];"
                         : "=f"(xv[j]) : "r"(xa + (unsigned)j * (XS_STRIDE * 4)));
        unsigned long long a[8];
        #pragma unroll
        for (int j = 0; j < 8; j++)
            asm("mov.b64 %0, {%1,%2};" : "=l"(a[j]) : "f"(xv[2*j]), "f"(xv[2*j+1]));

        float b0, b1, b2, b3, b4, b5, b6, b7;
        unsigned wa = ws_base + (unsigned)k * (WS_STRIDE * 4);
        asm volatile("ld.shared.v4.f32 {%0,%1,%2,%3}, [%4];"
                     : "=f"(b0), "=f"(b1), "=f"(b2), "=f"(b3) : "r"(wa));
        asm volatile("ld.shared.v4.f32 {%0,%1,%2,%3}, [%4];"
                     : "=f"(b4), "=f"(b5), "=f"(b6), "=f"(b7) : "r"(wa + 16));
        unsigned long long bb[8];
        asm("mov.b64 %0, {%1,%1};" : "=l"(bb[0]) : "f"(b0));
        asm("mov.b64 %0, {%1,%1};" : "=l"(bb[1]) : "f"(b1));
        asm("mov.b64 %0, {%1,%1};" : "=l"(bb[2]) : "f"(b2));
        asm("mov.b64 %0, {%1,%1};" : "=l"(bb[3]) : "f"(b3));
        asm("mov.b64 %0, {%1,%1};" : "=l"(bb[4]) : "f"(b4));
        asm("mov.b64 %0, {%1,%1};" : "=l"(bb[5]) : "f"(b5));
        asm("mov.b64 %0, {%1,%1};" : "=l"(bb[6]) : "f"(b6));
        asm("mov.b64 %0, {%1,%1};" : "=l"(bb[7]) : "f"(b7));

        #pragma unroll
        for (int n = 0; n < 8; n++) {
            #pragma unroll
            for (int j = 0; j < 8; j++)
                asm("fma.rn.f32x2 %0, %1, %2, %0;"
                    : "+l"(acc[j][n]) : "l"(a[j]), "l"(bb[n]));
        }
    }

    // epilogue: rows m0+2j, m0+2j+1
    #pragma unroll
    for (int j = 0; j < 8; j++) {
        float lo[8], hi[8];
        #pragma unroll
        for (int n = 0; n < 8; n++)
            asm("mov.b64 {%0,%1}, %2;" : "=f"(lo[n]), "=f"(hi[n]) : "l"(acc[j][n]));
        #pragma unroll
        for (int h = 0; h < 2; h++) {
            int gr = r0 + m0 + j * 2 + h;
            if (gr < N) {
                const float* v = h ? hi : lo;
                float* p = Y + (size_t)gr * 128 + c0;
                float4 o0 = make_float4(v[0], v[1], v[2], v[3]);
                float4 o1 = make_float4(v[4], v[5], v[6], v[7]);
                if (accFlag) {
                    float4 y0 = *reinterpret_cast<float4*>(p);
                    float4 y1 = *reinterpret_cast<float4*>(p + 4);
                    o0.x += y0.x; o0.y += y0.y; o0.z += y0.z; o0.w += y0.w;
                    o1.x += y1.x; o1.y += y1.y; o1.z += y1.z; o1.w += y1.w;
                }
                *reinterpret_cast<float4*>(p)     = o0;
                *reinterpret_cast<float4*>(p + 4) = o1;
            }
        }
    }
}

// ---------------- combine: Z[b] <- sigmoid(Z[b]) (in place),
//                  E <- sigmoid(mean_b Z[b])  -------------------------------
__global__ void __launch_bounds__(256) combine_kernel(
    float* __restrict__ Z, float* __restrict__ E, int N)
{
    size_t i = (size_t)blockIdx.x * 256 + threadIdx.x;
    size_t tot = (size_t)N * 32;
    if (i >= tot) return;
    size_t o  = i * 4;
    size_t bs = (size_t)N * 128;
    float4 z0 = *reinterpret_cast<float4*>(Z + o);
    float4 z1 = *reinterpret_cast<float4*>(Z + o + bs);
    float4 z2 = *reinterpret_cast<float4*>(Z + o + 2 * bs);
    float4 z3 = *reinterpret_cast<float4*>(Z + o + 3 * bs);
    float4 m;
    m.x = sigf((z0.x + z1.x + z2.x + z3.x) * 0.25f);
    m.y = sigf((z0.y + z1.y + z2.y + z3.y) * 0.25f);
    m.z = sigf((z0.z + z1.z + z2.z + z3.z) * 0.25f);
    m.w = sigf((z0.w + z1.w + z2.w + z3.w) * 0.25f);
    *reinterpret_cast<float4*>(E + o) = m;
    z0.x = sigf(z0.x); z0.y = sigf(z0.y); z0.z = sigf(z0.z); z0.w = sigf(z0.w);
    z1.x = sigf(z1.x); z1.y = sigf(z1.y); z1.z = sigf(z1.z); z1.w = sigf(z1.w);
    z2.x = sigf(z2.x); z2.y = sigf(z2.y); z2.z = sigf(z2.z); z2.w = sigf(z2.w);
    z3.x = sigf(z3.x); z3.y = sigf(z3.y); z3.z = sigf(z3.z); z3.w = sigf(z3.w);
    *reinterpret_cast<float4*>(Z + o)          = z0;
    *reinterpret_cast<float4*>(Z + o + bs)     = z1;
    *reinterpret_cast<float4*>(Z + o + 2 * bs) = z2;
    *reinterpret_cast<float4*>(Z + o + 3 * bs) = z3;
}

// ---------------- launch ---------------------------------------------------
extern "C" void kernel_launch(void* const* d_in, const int* in_sizes, int n_in,
                              void* d_out, int out_size)
{
    const float* user_emb = (const float*)d_in[0];
    const float* item_emb = (const float*)d_in[1];
    const int*   rows     = (const int*)  d_in[2];
    const int*   cols     = (const int*)  d_in[3];
    const float* vals     = (const float*)d_in[4];
    const float* u_w      = (const float*)d_in[5];
    const float* i_w      = (const float*)d_in[6];
    const float* u_cat_w  = (const float*)d_in[7];
    const float* i_cat_w  = (const float*)d_in[8];
    float* out = (float*)d_out;

    static bool configured = false;
    if (!configured) {
        cudaFuncSetAttribute(gemm128_kernel,
                             cudaFuncAttributeMaxDynamicSharedMemorySize, GEMM_SMEM);
        configured = true;
    }

    float *ue, *ie, *ues, *ies, *su, *si;
    cudaGetSymbolAddress((void**)&ue,  g_ue);
    cudaGetSymbolAddress((void**)&ie,  g_ie);
    cudaGetSymbolAddress((void**)&ues, g_ues);
    cudaGetSymbolAddress((void**)&ies, g_ies);
    cudaGetSymbolAddress((void**)&su,  g_su);
    cudaGetSymbolAddress((void**)&si,  g_si);

    cudaMemcpyAsync(ue, user_emb, (size_t)U_N * DD * 4, cudaMemcpyDeviceToDevice);
    cudaMemcpyAsync(ie, item_emb, (size_t)I_N * DD * 4, cudaMemcpyDeviceToDevice);

    float* out_ue  = out;
    float* out_ie  = out + (size_t)U_N * DD;
    float* out_ues = out_ie + (size_t)I_N * DD;
    float* out_ies = out_ues + (size_t)BB * U_N * DD;

    const int totE = BB * NNZC;
    const int spmmBl = (int)(((long long)totE * 32 + 255) / 256);

    for (int l = 0; l < LL; l++) {
        cudaMemsetAsync(ues, 0, (size_t)BB * U_N * DD * 4);
        cudaMemsetAsync(ies, 0, (size_t)BB * I_N * DD * 4);

        spmm_kernel<<<spmmBl, 256>>>(rows, cols, vals, ie, ues, totE, NNZC, U_N, 1);
        spmm_kernel<<<spmmBl, 256>>>(rows, cols, vals, ue, ies, totE, NNZC, I_N, 0);

        gemm128_kernel<<<(BB * U_N + RPB - 1) / RPB, 256, GEMM_SMEM>>>(
            ues, u_w + (size_t)l * DD * DD, su, BB * U_N, 0);
        gemm128_kernel<<<(BB * I_N + RPB - 1) / RPB, 256, GEMM_SMEM>>>(
            ies, i_w + (size_t)l * DD * DD, si, BB * I_N, 0);

        combine_kernel<<<(U_N * 32 + 255) / 256, 256>>>(su, ue, U_N);
        combine_kernel<<<(I_N * 32 + 255) / 256, 256>>>(si, ie, I_N);

        int acc = (l > 0) ? 1 : 0;
        gemm128_kernel<<<(U_N + RPB - 1) / RPB, 256, GEMM_SMEM>>>(
            ue, u_cat_w + (size_t)l * DD * DD, out_ue, U_N, acc);
        gemm128_kernel<<<(I_N + RPB - 1) / RPB, 256, GEMM_SMEM>>>(
            ie, i_cat_w + (size_t)l * DD * DD, out_ie, I_N, acc);
        gemm128_kernel<<<(BB * U_N + RPB - 1) / RPB, 256, GEMM_SMEM>>>(
            su, u_cat_w + (size_t)l * DD * DD, out_ues, BB * U_N, acc);
        gemm128_kernel<<<(BB * I_N + RPB - 1) / RPB, 256, GEMM_SMEM>>>(
            si, i_cat_w + (size_t)l * DD * DD, out_ies, BB * I_N, acc);
    }
}

// round 6
// speedup vs baseline: 1.1463x; 1.0261x over previous
#include <cuda_runtime.h>
#include <cstdint>
#include <cstddef>

#define U_N  100000
#define I_N  50000
#define DD   128
#define BB   4
#define LL   2
#define NNZC 500000

// ---------------- scratch (device globals: allocation-guard-safe) ----------
__device__ float g_ue [U_N * DD];
__device__ float g_ie [I_N * DD];
__device__ float g_ues[BB * U_N * DD];
__device__ float g_ies[BB * I_N * DD];
__device__ float g_su [BB * U_N * DD];
__device__ float g_si [BB * I_N * DD];

__device__ __forceinline__ unsigned smem_u32(const void* p) {
    return (unsigned)__cvta_generic_to_shared(p);
}
__device__ __forceinline__ float sigf(float x) {
    return 1.0f / (1.0f + __expf(-x));
}

// ---------------- SPMM: one warp per edge, vector RED scatter --------------
__global__ void __launch_bounds__(256) spmm_kernel(
    const int* __restrict__ ridx, const int* __restrict__ cidx,
    const float* __restrict__ vals, const float* __restrict__ src,
    float* __restrict__ dst, int total, int nnz, int ndst, int dst_rows)
{
    int g = blockIdx.x * blockDim.x + threadIdx.x;
    int e = g >> 5;
    if (e >= total) return;
    int lane = g & 31;
    int r = __ldg(ridx + e);
    int c = __ldg(cidx + e);
    float v = __ldg(vals + e);
    int d = dst_rows ? r : c;
    int s = dst_rows ? c : r;
    int b = e / nnz;
    float4 x = __ldg(reinterpret_cast<const float4*>(src + (size_t)s * DD) + lane);
    float* p = dst + ((size_t)b * ndst + d) * DD + (size_t)lane * 4;
    asm volatile("red.global.add.v4.f32 [%0], {%1,%2,%3,%4};"
                 :: "l"(p), "f"(v * x.x), "f"(v * x.y), "f"(v * x.z), "f"(v * x.w)
                 : "memory");
}

// ---------------- GEMM: Y[N,128] = X[N,128] @ W[128,128] (+= if acc) -------
// 256 threads, 128-row x 128-col tile, 8x8 per-thread tile.
// XsT[k][row]  : X transposed -> row-pairs are adjacent => ld.v2.u64 gives
//                packed (row2j, row2j+1) operands with NO pack movs.
// Wd[k][2c]    : W duplicated -> ld.v2.u64 gives broadcast-packed operands
//                with NO dup movs.
// Inner loop per k: 6 LDS + 32 fma.rn.f32x2, zero ALU packing.
#define RPB        128
#define XT_STRIDE  132                   // floats per k-row (128 rows + pad)
#define WD_STRIDE  260                   // floats per k-row (256 dup + pad)
#define GEMM_SMEM  ((128 * XT_STRIDE + 128 * WD_STRIDE) * 4)   // 200,704 B

__global__ void __launch_bounds__(256, 1) gemm128_kernel(
    const float* __restrict__ X, const float* __restrict__ W,
    float* __restrict__ Y, int N, int accFlag)
{
    extern __shared__ float sm[];
    float* XsT = sm;                        // [128 k][132]
    float* Wd  = sm + 128 * XT_STRIDE;      // [128 k][260]
    const int tid = threadIdx.x;
    const int r0  = blockIdx.x * RPB;

    // --- load W [128x128] coalesced, store duplicated ---
    for (int t = 0; t < 16; t++) {
        int i   = tid + 256 * t;
        int row = i >> 5;
        int c4  = (i & 31) << 2;
        float4 w = *reinterpret_cast<const float4*>(W + row * 128 + c4);
        float* p = &Wd[row * WD_STRIDE + 2 * c4];
        *reinterpret_cast<float4*>(p)     = make_float4(w.x, w.x, w.y, w.y);
        *reinterpret_cast<float4*>(p + 4) = make_float4(w.z, w.z, w.w, w.w);
    }
    // --- load X tile, store TRANSPOSED (lanes own consecutive rows =>
    //     conflict-free STS; global 16B/lane reads amortized by L1 reuse) ---
    for (int t = 0; t < 16; t++) {
        int i   = tid + 256 * t;
        int row = i & 127;
        int c4  = (i >> 7) << 2;
        float4 x = make_float4(0.f, 0.f, 0.f, 0.f);
        int gr = r0 + row;
        if (gr < N) x = *reinterpret_cast<const float4*>(X + (size_t)gr * 128 + c4);
        XsT[(c4 + 0) * XT_STRIDE + row] = x.x;
        XsT[(c4 + 1) * XT_STRIDE + row] = x.y;
        XsT[(c4 + 2) * XT_STRIDE + row] = x.z;
        XsT[(c4 + 3) * XT_STRIDE + row] = x.w;
    }
    __syncthreads();

    const int m0 = (tid & 15) << 3;    // 8 rows per thread
    const int c0 = (tid >> 4) << 3;    // 8 cols per thread
    const unsigned xs_base = smem_u32(XsT) + (unsigned)m0 * 4;
    const unsigned wd_base = smem_u32(Wd)  + (unsigned)c0 * 8;

    unsigned long long acc[4][8];      // 4 row-pairs x 8 cols
    #pragma unroll
    for (int j = 0; j < 4; j++)
        #pragma unroll
        for (int n = 0; n < 8; n++) acc[j][n] = 0ULL;

    #pragma unroll 4
    for (int k = 0; k < 128; k++) {
        unsigned long long a[4];
        unsigned xa = xs_base + (unsigned)k * (XT_STRIDE * 4);
        asm volatile("ld.shared.v2.u64 {%0,%1}, [%2];" : "=l"(a[0]), "=l"(a[1]) : "r"(xa));
        asm volatile("ld.shared.v2.u64 {%0,%1}, [%2];" : "=l"(a[2]), "=l"(a[3]) : "r"(xa + 16));

        unsigned long long bb[8];
        unsigned wa = wd_base + (unsigned)k * (WD_STRIDE * 4);
        asm volatile("ld.shared.v2.u64 {%0,%1}, [%2];" : "=l"(bb[0]), "=l"(bb[1]) : "r"(wa));
        asm volatile("ld.shared.v2.u64 {%0,%1}, [%2];" : "=l"(bb[2]), "=l"(bb[3]) : "r"(wa + 16));
        asm volatile("ld.shared.v2.u64 {%0,%1}, [%2];" : "=l"(bb[4]), "=l"(bb[5]) : "r"(wa + 32));
        asm volatile("ld.shared.v2.u64 {%0,%1}, [%2];" : "=l"(bb[6]), "=l"(bb[7]) : "r"(wa + 48));

        #pragma unroll
        for (int n = 0; n < 8; n++) {
            #pragma unroll
            for (int j = 0; j < 4; j++)
                asm("fma.rn.f32x2 %0, %1, %2, %0;"
                    : "+l"(acc[j][n]) : "l"(a[j]), "l"(bb[n]));
        }
    }

    // epilogue: rows m0+2j, m0+2j+1
    #pragma unroll
    for (int j = 0; j < 4; j++) {
        float lo[8], hi[8];
        #pragma unroll
        for (int n = 0; n < 8; n++)
            asm("mov.b64 {%0,%1}, %2;" : "=f"(lo[n]), "=f"(hi[n]) : "l"(acc[j][n]));
        #pragma unroll
        for (int h = 0; h < 2; h++) {
            int gr = r0 + m0 + j * 2 + h;
            if (gr < N) {
                const float* v = h ? hi : lo;
                float* p = Y + (size_t)gr * 128 + c0;
                float4 o0 = make_float4(v[0], v[1], v[2], v[3]);
                float4 o1 = make_float4(v[4], v[5], v[6], v[7]);
                if (accFlag) {
                    float4 y0 = *reinterpret_cast<float4*>(p);
                    float4 y1 = *reinterpret_cast<float4*>(p + 4);
                    o0.x += y0.x; o0.y += y0.y; o0.z += y0.z; o0.w += y0.w;
                    o1.x += y1.x; o1.y += y1.y; o1.z += y1.z; o1.w += y1.w;
                }
                *reinterpret_cast<float4*>(p)     = o0;
                *reinterpret_cast<float4*>(p + 4) = o1;
            }
        }
    }
}

// ---------------- combine: Z[b] <- sigmoid(Z[b]) (in place),
//                  E <- sigmoid(mean_b Z[b])  -------------------------------
__global__ void __launch_bounds__(256) combine_kernel(
    float* __restrict__ Z, float* __restrict__ E, int N)
{
    size_t i = (size_t)blockIdx.x * 256 + threadIdx.x;
    size_t tot = (size_t)N * 32;
    if (i >= tot) return;
    size_t o  = i * 4;
    size_t bs = (size_t)N * 128;
    float4 z0 = *reinterpret_cast<float4*>(Z + o);
    float4 z1 = *reinterpret_cast<float4*>(Z + o + bs);
    float4 z2 = *reinterpret_cast<float4*>(Z + o + 2 * bs);
    float4 z3 = *reinterpret_cast<float4*>(Z + o + 3 * bs);
    float4 m;
    m.x = sigf((z0.x + z1.x + z2.x + z3.x) * 0.25f);
    m.y = sigf((z0.y + z1.y + z2.y + z3.y) * 0.25f);
    m.z = sigf((z0.z + z1.z + z2.z + z3.z) * 0.25f);
    m.w = sigf((z0.w + z1.w + z2.w + z3.w) * 0.25f);
    *reinterpret_cast<float4*>(E + o) = m;
    z0.x = sigf(z0.x); z0.y = sigf(z0.y); z0.z = sigf(z0.z); z0.w = sigf(z0.w);
    z1.x = sigf(z1.x); z1.y = sigf(z1.y); z1.z = sigf(z1.z); z1.w = sigf(z1.w);
    z2.x = sigf(z2.x); z2.y = sigf(z2.y); z2.z = sigf(z2.z); z2.w = sigf(z2.w);
    z3.x = sigf(z3.x); z3.y = sigf(z3.y); z3.z = sigf(z3.z); z3.w = sigf(z3.w);
    *reinterpret_cast<float4*>(Z + o)          = z0;
    *reinterpret_cast<float4*>(Z + o + bs)     = z1;
    *reinterpret_cast<float4*>(Z + o + 2 * bs) = z2;
    *reinterpret_cast<float4*>(Z + o + 3 * bs) = z3;
}

// ---------------- launch ---------------------------------------------------
extern "C" void kernel_launch(void* const* d_in, const int* in_sizes, int n_in,
                              void* d_out, int out_size)
{
    const float* user_emb = (const float*)d_in[0];
    const float* item_emb = (const float*)d_in[1];
    const int*   rows     = (const int*)  d_in[2];
    const int*   cols     = (const int*)  d_in[3];
    const float* vals     = (const float*)d_in[4];
    const float* u_w      = (const float*)d_in[5];
    const float* i_w      = (const float*)d_in[6];
    const float* u_cat_w  = (const float*)d_in[7];
    const float* i_cat_w  = (const float*)d_in[8];
    float* out = (float*)d_out;

    static bool configured = false;
    if (!configured) {
        cudaFuncSetAttribute(gemm128_kernel,
                             cudaFuncAttributeMaxDynamicSharedMemorySize, GEMM_SMEM);
        configured = true;
    }

    float *ue, *ie, *ues, *ies, *su, *si;
    cudaGetSymbolAddress((void**)&ue,  g_ue);
    cudaGetSymbolAddress((void**)&ie,  g_ie);
    cudaGetSymbolAddress((void**)&ues, g_ues);
    cudaGetSymbolAddress((void**)&ies, g_ies);
    cudaGetSymbolAddress((void**)&su,  g_su);
    cudaGetSymbolAddress((void**)&si,  g_si);

    cudaMemcpyAsync(ue, user_emb, (size_t)U_N * DD * 4, cudaMemcpyDeviceToDevice);
    cudaMemcpyAsync(ie, item_emb, (size_t)I_N * DD * 4, cudaMemcpyDeviceToDevice);

    float* out_ue  = out;
    float* out_ie  = out + (size_t)U_N * DD;
    float* out_ues = out_ie + (size_t)I_N * DD;
    float* out_ies = out_ues + (size_t)BB * U_N * DD;

    const int totE = BB * NNZC;
    const int spmmBl = (int)(((long long)totE * 32 + 255) / 256);

    for (int l = 0; l < LL; l++) {
        cudaMemsetAsync(ues, 0, (size_t)BB * U_N * DD * 4);
        cudaMemsetAsync(ies, 0, (size_t)BB * I_N * DD * 4);

        spmm_kernel<<<spmmBl, 256>>>(rows, cols, vals, ie, ues, totE, NNZC, U_N, 1);
        spmm_kernel<<<spmmBl, 256>>>(rows, cols, vals, ue, ies, totE, NNZC, I_N, 0);

        gemm128_kernel<<<(BB * U_N + RPB - 1) / RPB, 256, GEMM_SMEM>>>(
            ues, u_w + (size_t)l * DD * DD, su, BB * U_N, 0);
        gemm128_kernel<<<(BB * I_N + RPB - 1) / RPB, 256, GEMM_SMEM>>>(
            ies, i_w + (size_t)l * DD * DD, si, BB * I_N, 0);

        combine_kernel<<<(U_N * 32 + 255) / 256, 256>>>(su, ue, U_N);
        combine_kernel<<<(I_N * 32 + 255) / 256, 256>>>(si, ie, I_N);

        int acc = (l > 0) ? 1 : 0;
        gemm128_kernel<<<(U_N + RPB - 1) / RPB, 256, GEMM_SMEM>>>(
            ue, u_cat_w + (size_t)l * DD * DD, out_ue, U_N, acc);
        gemm128_kernel<<<(I_N + RPB - 1) / RPB, 256, GEMM_SMEM>>>(
            ie, i_cat_w + (size_t)l * DD * DD, out_ie, I_N, acc);
        gemm128_kernel<<<(BB * U_N + RPB - 1) / RPB, 256, GEMM_SMEM>>>(
            su, u_cat_w + (size_t)l * DD * DD, out_ues, BB * U_N, acc);
        gemm128_kernel<<<(BB * I_N + RPB - 1) / RPB, 256, GEMM_SMEM>>>(
            si, i_cat_w + (size_t)l * DD * DD, out_ies, BB * I_N, acc);
    }
}